// round 1
// baseline (speedup 1.0000x reference)
#include <cuda_runtime.h>

// Problem constants
#define BB   4
#define TT   2048
#define CC   1024
#define HH   16
#define DD   64
#define MROWS (BB*TT)      // 8192

// Scratch (static device globals — no allocations allowed)
__device__ float g_q[BB*HH*TT*DD];   // [B,H,T,d]
__device__ float g_k[BB*HH*TT*DD];
__device__ float g_v[BB*HH*TT*DD];
__device__ float g_y[BB*TT*CC];      // attention output, [B,T,C]

// ---------------------------------------------------------------------------
// Kernel 1: QKV GEMM.  X[8192,1024] @ W[1024,3072] + bias -> scatter to q/k/v
// 128x128 tile, BK=16, 256 threads, 8x8 per thread.
// ---------------------------------------------------------------------------
__global__ __launch_bounds__(256, 2)
void qkv_kernel(const float* __restrict__ X, const float* __restrict__ W,
                const float* __restrict__ bias)
{
    __shared__ float As[16][132];   // A transposed: As[k][m]
    __shared__ float Bs[16][132];   // Bs[k][n]

    const int tid  = threadIdx.x;
    const int m0   = blockIdx.y * 128;
    const int n0   = blockIdx.x * 128;
    const int ty   = tid >> 4, tx = tid & 15;
    const int row8 = ty * 8,  col8 = tx * 8;

    float acc[8][8];
#pragma unroll
    for (int i = 0; i < 8; i++)
#pragma unroll
        for (int j = 0; j < 8; j++) acc[i][j] = 0.f;

    for (int k0 = 0; k0 < CC; k0 += 16) {
#pragma unroll
        for (int it = 0; it < 2; it++) {
            int idx = tid + 256 * it;           // 0..511
            int r   = idx >> 2;                 // 0..127
            int kq  = (idx & 3) * 4;            // 0,4,8,12
            float4 v = *(const float4*)(X + (size_t)(m0 + r) * CC + k0 + kq);
            As[kq + 0][r] = v.x; As[kq + 1][r] = v.y;
            As[kq + 2][r] = v.z; As[kq + 3][r] = v.w;
        }
#pragma unroll
        for (int it = 0; it < 2; it++) {
            int idx = tid + 256 * it;
            int kk  = idx >> 5;                 // 0..15
            int nq  = (idx & 31) * 4;           // 0..124
            *(float4*)&Bs[kk][nq] =
                *(const float4*)(W + (size_t)(k0 + kk) * 3072 + n0 + nq);
        }
        __syncthreads();
#pragma unroll
        for (int kk = 0; kk < 16; kk++) {
            float a[8], bb[8];
            *(float4*)&a[0]  = *(float4*)&As[kk][row8];
            *(float4*)&a[4]  = *(float4*)&As[kk][row8 + 4];
            *(float4*)&bb[0] = *(float4*)&Bs[kk][col8];
            *(float4*)&bb[4] = *(float4*)&Bs[kk][col8 + 4];
#pragma unroll
            for (int i = 0; i < 8; i++)
#pragma unroll
                for (int j = 0; j < 8; j++)
                    acc[i][j] = fmaf(a[i], bb[j], acc[i][j]);
        }
        __syncthreads();
    }

    // Epilogue: scatter into q/k/v in [B,H,T,d] layout, add bias.
    int sel = n0 >> 10;                          // 0=q, 1=k, 2=v (tile inside one)
    float* out = (sel == 0) ? g_q : ((sel == 1) ? g_k : g_v);
    int c0 = (n0 + col8) & 1023;
    int h  = c0 >> 6;
    int dd = c0 & 63;                            // 8-aligned, inside one head
    float bv[8];
#pragma unroll
    for (int j = 0; j < 8; j++) bv[j] = bias[n0 + col8 + j];
#pragma unroll
    for (int i = 0; i < 8; i++) {
        int m = m0 + row8 + i;
        int b = m >> 11, t = m & 2047;
        float* p = out + ((size_t)((b * HH + h) * TT + t)) * DD + dd;
        float4 v0 = make_float4(acc[i][0] + bv[0], acc[i][1] + bv[1],
                                acc[i][2] + bv[2], acc[i][3] + bv[3]);
        float4 v1 = make_float4(acc[i][4] + bv[4], acc[i][5] + bv[5],
                                acc[i][6] + bv[6], acc[i][7] + bv[7]);
        *(float4*)p       = v0;
        *(float4*)(p + 4) = v1;
    }
}

// ---------------------------------------------------------------------------
// Kernel 2: Flash attention (causal), fp32, online softmax.
// One CTA = one (b,h) and 128 queries. Key blocks of 64. 256 threads.
// Thread tile: 8 query rows x 4 cols (keys for S, head-dims for O).
// Smem: Qt[64][132] (d-major), Vs[64][68], union{Kt[64][68], Ps[128][68]}.
// ---------------------------------------------------------------------------
#define ATTN_SMEM_FLOATS (64*132 + 64*68 + 128*68)   // 21504 floats = 86016 B
#define ATTN_SMEM_BYTES  (ATTN_SMEM_FLOATS * 4)

__global__ __launch_bounds__(256, 2)
void attn_kernel()
{
    extern __shared__ float smem[];
    float (*Qt)[132] = (float(*)[132])smem;                       // [d][query]
    float (*Vs)[68]  = (float(*)[68])(smem + 64 * 132);           // [key][d]
    float (*Kt)[68]  = (float(*)[68])(smem + 64 * 132 + 64 * 68); // [d][key]
    float (*Ps)[68]  = (float(*)[68])(smem + 64 * 132 + 64 * 68); // [query][key] (aliases Kt)

    const int tid  = threadIdx.x;
    const int ty   = tid >> 4, tx = tid & 15;
    const int row8 = ty * 8;          // query rows owned (8)
    const int col4 = tx * 4;          // key cols / head-dim cols owned (4)

    const int q0 = blockIdx.x * 128;
    const int bh = blockIdx.y;        // b*16 + h
    const float* qbase = g_q + ((size_t)bh * TT + q0) * DD;

    // Load Q tile (scaled by 1/sqrt(d)) transposed: Qt[d][i]
    const float scale = 0.125f;
#pragma unroll
    for (int it = 0; it < 8; it++) {
        int idx = tid + 256 * it;     // 0..2047
        int r   = idx >> 4;           // 0..127
        int dq  = (idx & 15) * 4;     // 0..60
        float4 v = *(const float4*)(qbase + (size_t)r * DD + dq);
        Qt[dq + 0][r] = v.x * scale; Qt[dq + 1][r] = v.y * scale;
        Qt[dq + 2][r] = v.z * scale; Qt[dq + 3][r] = v.w * scale;
    }

    float m_i[8], l_i[8], O[8][4];
#pragma unroll
    for (int i = 0; i < 8; i++) {
        m_i[i] = -1e30f; l_i[i] = 0.f;
#pragma unroll
        for (int c = 0; c < 4; c++) O[i][c] = 0.f;
    }

    const int maskStart = q0 >> 6;
    const int nblk      = maskStart + 2;

    for (int kb = 0; kb < nblk; kb++) {
        __syncthreads();   // prior Ps reads / Vs reads complete before overwrite

        // Load K (transposed) and V tiles for this key block
        const float* kbase = g_k + ((size_t)bh * TT + kb * 64) * DD;
        const float* vbase = g_v + ((size_t)bh * TT + kb * 64) * DD;
#pragma unroll
        for (int it = 0; it < 4; it++) {
            int idx = tid + 256 * it; // 0..1023
            int r   = idx >> 4;       // 0..63
            int dq  = (idx & 15) * 4;
            float4 kv = *(const float4*)(kbase + (size_t)r * DD + dq);
            Kt[dq + 0][r] = kv.x; Kt[dq + 1][r] = kv.y;
            Kt[dq + 2][r] = kv.z; Kt[dq + 3][r] = kv.w;
            *(float4*)&Vs[r][dq] = *(const float4*)(vbase + (size_t)r * DD + dq);
        }
        __syncthreads();

        // S = Q K^T  (thread: 8x4 of the 128x64 score tile)
        float s[8][4];
#pragma unroll
        for (int i = 0; i < 8; i++)
#pragma unroll
            for (int j = 0; j < 4; j++) s[i][j] = 0.f;

#pragma unroll 4
        for (int dd = 0; dd < 64; dd++) {
            float4 a0 = *(float4*)&Qt[dd][row8];
            float4 a1 = *(float4*)&Qt[dd][row8 + 4];
            float4 bq = *(float4*)&Kt[dd][col4];
            float a[8] = {a0.x, a0.y, a0.z, a0.w, a1.x, a1.y, a1.z, a1.w};
            float bb[4] = {bq.x, bq.y, bq.z, bq.w};
#pragma unroll
            for (int i = 0; i < 8; i++)
#pragma unroll
                for (int j = 0; j < 4; j++)
                    s[i][j] = fmaf(a[i], bb[j], s[i][j]);
        }

        // Causal mask (only near/above the diagonal)
        if (kb >= maskStart) {
#pragma unroll
            for (int i = 0; i < 8; i++) {
                int gq = q0 + row8 + i;
#pragma unroll
                for (int j = 0; j < 4; j++) {
                    int gk = kb * 64 + col4 + j;
                    if (gk > gq) s[i][j] = -1e30f;
                }
            }
        }

        // Row max across 64 cols (4 local + shfl over 16 lanes)
        float rmax[8], rsum[8];
#pragma unroll
        for (int i = 0; i < 8; i++) {
            float v = fmaxf(fmaxf(s[i][0], s[i][1]), fmaxf(s[i][2], s[i][3]));
#pragma unroll
            for (int o = 1; o < 16; o <<= 1)
                v = fmaxf(v, __shfl_xor_sync(0xffffffffu, v, o));
            rmax[i] = v;
        }

        // Online softmax update
#pragma unroll
        for (int i = 0; i < 8; i++) {
            float mnew  = fmaxf(m_i[i], rmax[i]);
            float alpha = __expf(m_i[i] - mnew);
            m_i[i] = mnew;
            float ps = 0.f;
#pragma unroll
            for (int j = 0; j < 4; j++) {
                s[i][j] = __expf(s[i][j] - mnew);   // s becomes P
                ps += s[i][j];
            }
#pragma unroll
            for (int o = 1; o < 16; o <<= 1)
                ps += __shfl_xor_sync(0xffffffffu, ps, o);
            rsum[i] = ps;
            l_i[i]  = l_i[i] * alpha + rsum[i];
#pragma unroll
            for (int c = 0; c < 4; c++) O[i][c] *= alpha;
        }

        __syncthreads();   // Kt reads done before Ps writes (same buffer)
#pragma unroll
        for (int i = 0; i < 8; i++)
            *(float4*)&Ps[row8 + i][col4] =
                make_float4(s[i][0], s[i][1], s[i][2], s[i][3]);
        __syncthreads();   // Ps ready

        // O += P @ V  (thread: 8 rows x 4 head-dims)
#pragma unroll 2
        for (int j = 0; j < 64; j += 4) {
            float4 pa[8];
#pragma unroll
            for (int i = 0; i < 8; i++) pa[i] = *(float4*)&Ps[row8 + i][j];
            float4 b0 = *(float4*)&Vs[j + 0][col4];
            float4 b1 = *(float4*)&Vs[j + 1][col4];
            float4 b2 = *(float4*)&Vs[j + 2][col4];
            float4 b3 = *(float4*)&Vs[j + 3][col4];
#pragma unroll
            for (int i = 0; i < 8; i++) {
                O[i][0] = fmaf(pa[i].x, b0.x, O[i][0]);
                O[i][0] = fmaf(pa[i].y, b1.x, O[i][0]);
                O[i][0] = fmaf(pa[i].z, b2.x, O[i][0]);
                O[i][0] = fmaf(pa[i].w, b3.x, O[i][0]);
                O[i][1] = fmaf(pa[i].x, b0.y, O[i][1]);
                O[i][1] = fmaf(pa[i].y, b1.y, O[i][1]);
                O[i][1] = fmaf(pa[i].z, b2.y, O[i][1]);
                O[i][1] = fmaf(pa[i].w, b3.y, O[i][1]);
                O[i][2] = fmaf(pa[i].x, b0.z, O[i][2]);
                O[i][2] = fmaf(pa[i].y, b1.z, O[i][2]);
                O[i][2] = fmaf(pa[i].z, b2.z, O[i][2]);
                O[i][2] = fmaf(pa[i].w, b3.z, O[i][2]);
                O[i][3] = fmaf(pa[i].x, b0.w, O[i][3]);
                O[i][3] = fmaf(pa[i].y, b1.w, O[i][3]);
                O[i][3] = fmaf(pa[i].z, b2.w, O[i][3]);
                O[i][3] = fmaf(pa[i].w, b3.w, O[i][3]);
            }
        }
    }

    // Normalize and write to g_y in [B,T,C] layout
    const int b = bh >> 4, h = bh & 15;
#pragma unroll
    for (int i = 0; i < 8; i++) {
        float inv = 1.f / l_i[i];
        int t = q0 + row8 + i;
        float* p = g_y + ((size_t)b * TT + t) * CC + h * DD + col4;
        *(float4*)p = make_float4(O[i][0] * inv, O[i][1] * inv,
                                  O[i][2] * inv, O[i][3] * inv);
    }
}

// ---------------------------------------------------------------------------
// Kernel 3: projection GEMM.  g_y[8192,1024] @ W_proj[1024,1024] + b -> out
// ---------------------------------------------------------------------------
__global__ __launch_bounds__(256, 2)
void proj_kernel(const float* __restrict__ W, const float* __restrict__ bias,
                 float* __restrict__ out)
{
    __shared__ float As[16][132];
    __shared__ float Bs[16][132];

    const int tid  = threadIdx.x;
    const int m0   = blockIdx.y * 128;
    const int n0   = blockIdx.x * 128;
    const int ty   = tid >> 4, tx = tid & 15;
    const int row8 = ty * 8,  col8 = tx * 8;

    float acc[8][8];
#pragma unroll
    for (int i = 0; i < 8; i++)
#pragma unroll
        for (int j = 0; j < 8; j++) acc[i][j] = 0.f;

    for (int k0 = 0; k0 < CC; k0 += 16) {
#pragma unroll
        for (int it = 0; it < 2; it++) {
            int idx = tid + 256 * it;
            int r   = idx >> 2;
            int kq  = (idx & 3) * 4;
            float4 v = *(const float4*)(g_y + (size_t)(m0 + r) * CC + k0 + kq);
            As[kq + 0][r] = v.x; As[kq + 1][r] = v.y;
            As[kq + 2][r] = v.z; As[kq + 3][r] = v.w;
        }
#pragma unroll
        for (int it = 0; it < 2; it++) {
            int idx = tid + 256 * it;
            int kk  = idx >> 5;
            int nq  = (idx & 31) * 4;
            *(float4*)&Bs[kk][nq] =
                *(const float4*)(W + (size_t)(k0 + kk) * CC + n0 + nq);
        }
        __syncthreads();
#pragma unroll
        for (int kk = 0; kk < 16; kk++) {
            float a[8], bb[8];
            *(float4*)&a[0]  = *(float4*)&As[kk][row8];
            *(float4*)&a[4]  = *(float4*)&As[kk][row8 + 4];
            *(float4*)&bb[0] = *(float4*)&Bs[kk][col8];
            *(float4*)&bb[4] = *(float4*)&Bs[kk][col8 + 4];
#pragma unroll
            for (int i = 0; i < 8; i++)
#pragma unroll
                for (int j = 0; j < 8; j++)
                    acc[i][j] = fmaf(a[i], bb[j], acc[i][j]);
        }
        __syncthreads();
    }

    float bv[8];
#pragma unroll
    for (int j = 0; j < 8; j++) bv[j] = bias[n0 + col8 + j];
#pragma unroll
    for (int i = 0; i < 8; i++) {
        int m = m0 + row8 + i;
        float* p = out + (size_t)m * CC + n0 + col8;
        float4 v0 = make_float4(acc[i][0] + bv[0], acc[i][1] + bv[1],
                                acc[i][2] + bv[2], acc[i][3] + bv[3]);
        float4 v1 = make_float4(acc[i][4] + bv[4], acc[i][5] + bv[5],
                                acc[i][6] + bv[6], acc[i][7] + bv[7]);
        *(float4*)p       = v0;
        *(float4*)(p + 4) = v1;
    }
}

// ---------------------------------------------------------------------------
extern "C" void kernel_launch(void* const* d_in, const int* in_sizes, int n_in,
                              void* d_out, int out_size)
{
    (void)in_sizes; (void)n_in; (void)out_size;
    const float* x      = (const float*)d_in[0];
    const float* W_attn = (const float*)d_in[1];
    const float* b_attn = (const float*)d_in[2];
    const float* W_proj = (const float*)d_in[3];
    const float* b_proj = (const float*)d_in[4];
    float* out = (float*)d_out;

    // Opt-in to >48KB dynamic smem for the attention kernel (host attr set,
    // not a stream op — safe under graph capture; idempotent).
    cudaFuncSetAttribute(attn_kernel,
                         cudaFuncAttributeMaxDynamicSharedMemorySize,
                         ATTN_SMEM_BYTES);

    qkv_kernel <<<dim3(3072 / 128, MROWS / 128), 256>>>(x, W_attn, b_attn);
    attn_kernel<<<dim3(TT / 128, BB * HH), 256, ATTN_SMEM_BYTES>>>();
    proj_kernel<<<dim3(CC / 128, MROWS / 128), 256>>>(W_proj, b_proj, out);
}

// round 8
// speedup vs baseline: 1.0352x; 1.0352x over previous
#include <cuda_runtime.h>

// Problem constants
#define BB   4
#define TT   2048
#define CC   1024
#define HH   16
#define DD   64
#define MROWS (BB*TT)      // 8192

// Scratch (static device globals — no allocations allowed)
__device__ float g_q[BB*HH*TT*DD];   // [B,H,T,d]
__device__ float g_k[BB*HH*TT*DD];
__device__ float g_v[BB*HH*TT*DD];
__device__ float g_y[BB*TT*CC];      // attention output, [B,T,C]

// ---------------------------------------------------------------------------
// Kernel 1: QKV GEMM.  X[8192,1024] @ W[1024,3072] + bias -> scatter to q/k/v
// 128x128 tile, BK=16, 256 threads, 8x8 per thread.
// B stored half-interleaved: physical 16B chunk c holds logical column chunk
// jl = ((c&15)<<1)|(c>>4).  Fragment reads Bs[kk][4tx] / Bs[kk][64+4tx] then
// hit all 32 banks exactly once per phase (conflict-free; R1 was 2-way).
// ---------------------------------------------------------------------------
__global__ __launch_bounds__(256, 2)
void qkv_kernel(const float* __restrict__ X, const float* __restrict__ W,
                const float* __restrict__ bias)
{
    __shared__ float As[16][132];   // A transposed: As[k][m]
    __shared__ float Bs[16][132];   // Bs[k][interleaved n]

    const int tid  = threadIdx.x;
    const int m0   = blockIdx.y * 128;
    const int n0   = blockIdx.x * 128;
    const int ty   = tid >> 4, tx = tid & 15;
    const int row8 = ty * 8,  col8 = tx * 8;

    float acc[8][8];
#pragma unroll
    for (int i = 0; i < 8; i++)
#pragma unroll
        for (int j = 0; j < 8; j++) acc[i][j] = 0.f;

    for (int k0 = 0; k0 < CC; k0 += 16) {
#pragma unroll
        for (int it = 0; it < 2; it++) {
            int idx = tid + 256 * it;           // 0..511
            int r   = idx >> 2;                 // 0..127
            int kq  = (idx & 3) * 4;            // 0,4,8,12
            float4 v = *(const float4*)(X + (size_t)(m0 + r) * CC + k0 + kq);
            As[kq + 0][r] = v.x; As[kq + 1][r] = v.y;
            As[kq + 2][r] = v.z; As[kq + 3][r] = v.w;
        }
#pragma unroll
        for (int it = 0; it < 2; it++) {
            int idx = tid + 256 * it;
            int kk  = idx >> 5;                 // 0..15
            int c   = idx & 31;                 // physical chunk
            int jl  = ((c & 15) << 1) | (c >> 4);   // logical chunk
            *(float4*)&Bs[kk][4 * c] =
                *(const float4*)(W + (size_t)(k0 + kk) * 3072 + n0 + 4 * jl);
        }
        __syncthreads();
#pragma unroll
        for (int kk = 0; kk < 16; kk++) {
            float a[8], bb[8];
            *(float4*)&a[0]  = *(float4*)&As[kk][row8];
            *(float4*)&a[4]  = *(float4*)&As[kk][row8 + 4];
            *(float4*)&bb[0] = *(float4*)&Bs[kk][4 * tx];        // cols 8tx..+3
            *(float4*)&bb[4] = *(float4*)&Bs[kk][64 + 4 * tx];   // cols 8tx+4..+7
#pragma unroll
            for (int i = 0; i < 8; i++)
#pragma unroll
                for (int j = 0; j < 8; j++)
                    acc[i][j] = fmaf(a[i], bb[j], acc[i][j]);
        }
        __syncthreads();
    }

    // Epilogue: scatter into q/k/v in [B,H,T,d] layout, add bias.
    int sel = n0 >> 10;                          // 0=q, 1=k, 2=v
    float* out = (sel == 0) ? g_q : ((sel == 1) ? g_k : g_v);
    int c0 = (n0 + col8) & 1023;
    int h  = c0 >> 6;
    int dd = c0 & 63;
    float bv[8];
#pragma unroll
    for (int j = 0; j < 8; j++) bv[j] = bias[n0 + col8 + j];
#pragma unroll
    for (int i = 0; i < 8; i++) {
        int m = m0 + row8 + i;
        int b = m >> 11, t = m & 2047;
        float* p = out + ((size_t)((b * HH + h) * TT + t)) * DD + dd;
        float4 v0 = make_float4(acc[i][0] + bv[0], acc[i][1] + bv[1],
                                acc[i][2] + bv[2], acc[i][3] + bv[3]);
        float4 v1 = make_float4(acc[i][4] + bv[4], acc[i][5] + bv[5],
                                acc[i][6] + bv[6], acc[i][7] + bv[7]);
        *(float4*)p       = v0;
        *(float4*)(p + 4) = v1;
    }
}

// ---------------------------------------------------------------------------
// Kernel 2: Flash attention (causal), fp32, online softmax.
// BYTE-IDENTICAL to the Round-1 pass.
// ---------------------------------------------------------------------------
#define ATTN_SMEM_FLOATS (64*132 + 64*68 + 128*68)   // 21504 floats = 86016 B
#define ATTN_SMEM_BYTES  (ATTN_SMEM_FLOATS * 4)

__global__ __launch_bounds__(256, 2)
void attn_kernel()
{
    extern __shared__ float smem[];
    float (*Qt)[132] = (float(*)[132])smem;                       // [d][query]
    float (*Vs)[68]  = (float(*)[68])(smem + 64 * 132);           // [key][d]
    float (*Kt)[68]  = (float(*)[68])(smem + 64 * 132 + 64 * 68); // [d][key]
    float (*Ps)[68]  = (float(*)[68])(smem + 64 * 132 + 64 * 68); // aliases Kt

    const int tid  = threadIdx.x;
    const int ty   = tid >> 4, tx = tid & 15;
    const int row8 = ty * 8;
    const int col4 = tx * 4;

    const int q0 = blockIdx.x * 128;
    const int bh = blockIdx.y;        // b*16 + h
    const float* qbase = g_q + ((size_t)bh * TT + q0) * DD;

    const float scale = 0.125f;
#pragma unroll
    for (int it = 0; it < 8; it++) {
        int idx = tid + 256 * it;
        int r   = idx >> 4;
        int dq  = (idx & 15) * 4;
        float4 v = *(const float4*)(qbase + (size_t)r * DD + dq);
        Qt[dq + 0][r] = v.x * scale; Qt[dq + 1][r] = v.y * scale;
        Qt[dq + 2][r] = v.z * scale; Qt[dq + 3][r] = v.w * scale;
    }

    float m_i[8], l_i[8], O[8][4];
#pragma unroll
    for (int i = 0; i < 8; i++) {
        m_i[i] = -1e30f; l_i[i] = 0.f;
#pragma unroll
        for (int c = 0; c < 4; c++) O[i][c] = 0.f;
    }

    const int maskStart = q0 >> 6;
    const int nblk      = maskStart + 2;

    for (int kb = 0; kb < nblk; kb++) {
        __syncthreads();

        const float* kbase = g_k + ((size_t)bh * TT + kb * 64) * DD;
        const float* vbase = g_v + ((size_t)bh * TT + kb * 64) * DD;
#pragma unroll
        for (int it = 0; it < 4; it++) {
            int idx = tid + 256 * it;
            int r   = idx >> 4;
            int dq  = (idx & 15) * 4;
            float4 kv = *(const float4*)(kbase + (size_t)r * DD + dq);
            Kt[dq + 0][r] = kv.x; Kt[dq + 1][r] = kv.y;
            Kt[dq + 2][r] = kv.z; Kt[dq + 3][r] = kv.w;
            *(float4*)&Vs[r][dq] = *(const float4*)(vbase + (size_t)r * DD + dq);
        }
        __syncthreads();

        float s[8][4];
#pragma unroll
        for (int i = 0; i < 8; i++)
#pragma unroll
            for (int j = 0; j < 4; j++) s[i][j] = 0.f;

#pragma unroll 4
        for (int dd = 0; dd < 64; dd++) {
            float4 a0 = *(float4*)&Qt[dd][row8];
            float4 a1 = *(float4*)&Qt[dd][row8 + 4];
            float4 bq = *(float4*)&Kt[dd][col4];
            float a[8] = {a0.x, a0.y, a0.z, a0.w, a1.x, a1.y, a1.z, a1.w};
            float bb[4] = {bq.x, bq.y, bq.z, bq.w};
#pragma unroll
            for (int i = 0; i < 8; i++)
#pragma unroll
                for (int j = 0; j < 4; j++)
                    s[i][j] = fmaf(a[i], bb[j], s[i][j]);
        }

        if (kb >= maskStart) {
#pragma unroll
            for (int i = 0; i < 8; i++) {
                int gq = q0 + row8 + i;
#pragma unroll
                for (int j = 0; j < 4; j++) {
                    int gk = kb * 64 + col4 + j;
                    if (gk > gq) s[i][j] = -1e30f;
                }
            }
        }

        float rmax[8], rsum[8];
#pragma unroll
        for (int i = 0; i < 8; i++) {
            float v = fmaxf(fmaxf(s[i][0], s[i][1]), fmaxf(s[i][2], s[i][3]));
#pragma unroll
            for (int o = 1; o < 16; o <<= 1)
                v = fmaxf(v, __shfl_xor_sync(0xffffffffu, v, o));
            rmax[i] = v;
        }

#pragma unroll
        for (int i = 0; i < 8; i++) {
            float mnew  = fmaxf(m_i[i], rmax[i]);
            float alpha = __expf(m_i[i] - mnew);
            m_i[i] = mnew;
            float ps = 0.f;
#pragma unroll
            for (int j = 0; j < 4; j++) {
                s[i][j] = __expf(s[i][j] - mnew);
                ps += s[i][j];
            }
#pragma unroll
            for (int o = 1; o < 16; o <<= 1)
                ps += __shfl_xor_sync(0xffffffffu, ps, o);
            rsum[i] = ps;
            l_i[i]  = l_i[i] * alpha + rsum[i];
#pragma unroll
            for (int c = 0; c < 4; c++) O[i][c] *= alpha;
        }

        __syncthreads();
#pragma unroll
        for (int i = 0; i < 8; i++)
            *(float4*)&Ps[row8 + i][col4] =
                make_float4(s[i][0], s[i][1], s[i][2], s[i][3]);
        __syncthreads();

#pragma unroll 2
        for (int j = 0; j < 64; j += 4) {
            float4 pa[8];
#pragma unroll
            for (int i = 0; i < 8; i++) pa[i] = *(float4*)&Ps[row8 + i][j];
            float4 b0 = *(float4*)&Vs[j + 0][col4];
            float4 b1 = *(float4*)&Vs[j + 1][col4];
            float4 b2 = *(float4*)&Vs[j + 2][col4];
            float4 b3 = *(float4*)&Vs[j + 3][col4];
#pragma unroll
            for (int i = 0; i < 8; i++) {
                O[i][0] = fmaf(pa[i].x, b0.x, O[i][0]);
                O[i][0] = fmaf(pa[i].y, b1.x, O[i][0]);
                O[i][0] = fmaf(pa[i].z, b2.x, O[i][0]);
                O[i][0] = fmaf(pa[i].w, b3.x, O[i][0]);
                O[i][1] = fmaf(pa[i].x, b0.y, O[i][1]);
                O[i][1] = fmaf(pa[i].y, b1.y, O[i][1]);
                O[i][1] = fmaf(pa[i].z, b2.y, O[i][1]);
                O[i][1] = fmaf(pa[i].w, b3.y, O[i][1]);
                O[i][2] = fmaf(pa[i].x, b0.z, O[i][2]);
                O[i][2] = fmaf(pa[i].y, b1.z, O[i][2]);
                O[i][2] = fmaf(pa[i].z, b2.z, O[i][2]);
                O[i][2] = fmaf(pa[i].w, b3.z, O[i][2]);
                O[i][3] = fmaf(pa[i].x, b0.w, O[i][3]);
                O[i][3] = fmaf(pa[i].y, b1.w, O[i][3]);
                O[i][3] = fmaf(pa[i].z, b2.w, O[i][3]);
                O[i][3] = fmaf(pa[i].w, b3.w, O[i][3]);
            }
        }
    }

    const int b = bh >> 4, h = bh & 15;
#pragma unroll
    for (int i = 0; i < 8; i++) {
        float inv = 1.f / l_i[i];
        int t = q0 + row8 + i;
        float* p = g_y + ((size_t)b * TT + t) * CC + h * DD + col4;
        *(float4*)p = make_float4(O[i][0] * inv, O[i][1] * inv,
                                  O[i][2] * inv, O[i][3] * inv);
    }
}

// ---------------------------------------------------------------------------
// Kernel 3: projection GEMM.  g_y[8192,1024] @ W_proj[1024,1024] + b -> out
// Same half-interleaved B layout as qkv_kernel.
// ---------------------------------------------------------------------------
__global__ __launch_bounds__(256, 2)
void proj_kernel(const float* __restrict__ W, const float* __restrict__ bias,
                 float* __restrict__ out)
{
    __shared__ float As[16][132];
    __shared__ float Bs[16][132];

    const int tid  = threadIdx.x;
    const int m0   = blockIdx.y * 128;
    const int n0   = blockIdx.x * 128;
    const int ty   = tid >> 4, tx = tid & 15;
    const int row8 = ty * 8,  col8 = tx * 8;

    float acc[8][8];
#pragma unroll
    for (int i = 0; i < 8; i++)
#pragma unroll
        for (int j = 0; j < 8; j++) acc[i][j] = 0.f;

    for (int k0 = 0; k0 < CC; k0 += 16) {
#pragma unroll
        for (int it = 0; it < 2; it++) {
            int idx = tid + 256 * it;
            int r   = idx >> 2;
            int kq  = (idx & 3) * 4;
            float4 v = *(const float4*)(g_y + (size_t)(m0 + r) * CC + k0 + kq);
            As[kq + 0][r] = v.x; As[kq + 1][r] = v.y;
            As[kq + 2][r] = v.z; As[kq + 3][r] = v.w;
        }
#pragma unroll
        for (int it = 0; it < 2; it++) {
            int idx = tid + 256 * it;
            int kk  = idx >> 5;
            int c   = idx & 31;
            int jl  = ((c & 15) << 1) | (c >> 4);
            *(float4*)&Bs[kk][4 * c] =
                *(const float4*)(W + (size_t)(k0 + kk) * CC + n0 + 4 * jl);
        }
        __syncthreads();
#pragma unroll
        for (int kk = 0; kk < 16; kk++) {
            float a[8], bb[8];
            *(float4*)&a[0]  = *(float4*)&As[kk][row8];
            *(float4*)&a[4]  = *(float4*)&As[kk][row8 + 4];
            *(float4*)&bb[0] = *(float4*)&Bs[kk][4 * tx];
            *(float4*)&bb[4] = *(float4*)&Bs[kk][64 + 4 * tx];
#pragma unroll
            for (int i = 0; i < 8; i++)
#pragma unroll
                for (int j = 0; j < 8; j++)
                    acc[i][j] = fmaf(a[i], bb[j], acc[i][j]);
        }
        __syncthreads();
    }

    float bv[8];
#pragma unroll
    for (int j = 0; j < 8; j++) bv[j] = bias[n0 + col8 + j];
#pragma unroll
    for (int i = 0; i < 8; i++) {
        int m = m0 + row8 + i;
        float* p = out + (size_t)m * CC + n0 + col8;
        float4 v0 = make_float4(acc[i][0] + bv[0], acc[i][1] + bv[1],
                                acc[i][2] + bv[2], acc[i][3] + bv[3]);
        float4 v1 = make_float4(acc[i][4] + bv[4], acc[i][5] + bv[5],
                                acc[i][6] + bv[6], acc[i][7] + bv[7]);
        *(float4*)p       = v0;
        *(float4*)(p + 4) = v1;
    }
}

// ---------------------------------------------------------------------------
extern "C" void kernel_launch(void* const* d_in, const int* in_sizes, int n_in,
                              void* d_out, int out_size)
{
    (void)in_sizes; (void)n_in; (void)out_size;
    const float* x      = (const float*)d_in[0];
    const float* W_attn = (const float*)d_in[1];
    const float* b_attn = (const float*)d_in[2];
    const float* W_proj = (const float*)d_in[3];
    const float* b_proj = (const float*)d_in[4];
    float* out = (float*)d_out;

    cudaFuncSetAttribute(attn_kernel,
                         cudaFuncAttributeMaxDynamicSharedMemorySize,
                         ATTN_SMEM_BYTES);

    qkv_kernel <<<dim3(3072 / 128, MROWS / 128), 256>>>(x, W_attn, b_attn);
    attn_kernel<<<dim3(TT / 128, BB * HH), 256, ATTN_SMEM_BYTES>>>();
    proj_kernel<<<dim3(CC / 128, MROWS / 128), 256>>>(W_proj, b_proj, out);
}